// round 15
// baseline (speedup 1.0000x reference)
#include <cuda_runtime.h>
#include <cuda_bf16.h>
#include <math.h>
#include <stdint.h>

typedef __nv_bfloat16 bf16;

// ---------------- problem constants ----------------
#define Bc     16
#define HDIM   224
#define CC     96
#define LL     (HDIM*HDIM)
#define NTOK   (Bc*LL)              // 802816
#define WSZ    7
#define NN     49
#define NWIN   32
#define BW     (Bc*NWIN*NWIN)       // 16384
#define NHH    3
#define HD     32
#define MLPH   384
#define SHIFTV 3
#define SCALEV 0.17677669529663687f
#define NUMTILES (NTOK/128)         // 6272
#define NUMTILES2 (NTOK/256)        // 3136
#define GRID   148

static const long long YE = (long long)NTOK * CC;
static const long long AE = (long long)BW * NHH * NN * NN;

// ---------------- scratch ----------------
__device__ bf16 g_hw [(size_t)NTOK * CC];
__device__ bf16 g_qkv[(size_t)NTOK * 288];
__device__ bf16 g_att[(size_t)NTOK * CC];

// ---------------- helpers ----------------
__device__ __forceinline__ uint32_t smem_u32(const void* p) {
    uint32_t a;
    asm("{ .reg .u64 t; cvta.to.shared.u64 t, %1; cvt.u32.u64 %0, t; }" : "=r"(a) : "l"(p));
    return a;
}
__device__ __forceinline__ void cp16(void* d, const void* s) {
    asm volatile("cp.async.cg.shared.global [%0], [%1], 16;" :: "r"(smem_u32(d)), "l"(s));
}
#define CPC() asm volatile("cp.async.commit_group;" ::: "memory")
#define CPW() asm volatile("cp.async.wait_group 0;" ::: "memory")

__device__ __forceinline__ void ldm_x4(uint32_t& r0, uint32_t& r1, uint32_t& r2, uint32_t& r3, uint32_t addr) {
    asm volatile("ldmatrix.sync.aligned.m8n8.x4.shared.b16 {%0,%1,%2,%3}, [%4];"
                 : "=r"(r0), "=r"(r1), "=r"(r2), "=r"(r3) : "r"(addr));
}
__device__ __forceinline__ void ldm_x4t(uint32_t& r0, uint32_t& r1, uint32_t& r2, uint32_t& r3, uint32_t addr) {
    asm volatile("ldmatrix.sync.aligned.m8n8.x4.trans.shared.b16 {%0,%1,%2,%3}, [%4];"
                 : "=r"(r0), "=r"(r1), "=r"(r2), "=r"(r3) : "r"(addr));
}
__device__ __forceinline__ void mma16816(float* c, uint32_t a0, uint32_t a1, uint32_t a2, uint32_t a3,
                                         uint32_t b0, uint32_t b1) {
    asm volatile("mma.sync.aligned.m16n8k16.row.col.f32.bf16.bf16.f32 "
                 "{%0,%1,%2,%3}, {%4,%5,%6,%7}, {%8,%9}, {%0,%1,%2,%3};"
                 : "+f"(c[0]), "+f"(c[1]), "+f"(c[2]), "+f"(c[3])
                 : "r"(a0), "r"(a1), "r"(a2), "r"(a3), "r"(b0), "r"(b1));
}

__device__ __forceinline__ float wred(float v) {
    #pragma unroll
    for (int o = 16; o; o >>= 1) v += __shfl_xor_sync(0xffffffffu, v, o);
    return v;
}

__device__ __forceinline__ float fast_gelu(float x) {
    float t = x * (1.5957691216057308f + 0.07135481627f * x * x);
    return x / (1.f + __expf(-t));
}

__device__ __forceinline__ int winrow_to_token(int row) {
    int n  = row % NN;  int w = row / NN;
    int wj = w % NWIN;  int t = w / NWIN;
    int wi = t % NWIN;  int bb = t / NWIN;
    int i = n / WSZ, j = n % WSZ;
    int r = wi*WSZ + i + SHIFTV; if (r >= HDIM) r -= HDIM;
    int c = wj*WSZ + j + SHIFTV; if (c >= HDIM) c -= HDIM;
    return bb*LL + r*HDIM + c;
}

// =====================================================================
// qkv kernel: fused LN1 + gather + GEMM (96->288), 2 CTAs/SM [unchanged]
// =====================================================================
__global__ void __launch_bounds__(512, 2)
qkv_kernel(const float* __restrict__ x, const float* __restrict__ Wq,
           const float* __restrict__ bq, const float* __restrict__ g1,
           const float* __restrict__ b1, bf16* __restrict__ out)
{
    extern __shared__ __align__(16) char sm[];
    bf16*  sW   = (bf16*)sm;                       // 56832
    bf16*  sA   = (bf16*)(sm + 56832);             // 26624
    int*   stok = (int*)(sm + 83456);              // 512
    float* sbias= (float*)(sm + 83968);            // 1152
    float* sg   = (float*)(sm + 85120);            // 384
    float* sb   = (float*)(sm + 85504);            // 384  (total 85888)

    const int tid = threadIdx.x, warp = tid >> 5, lane = tid & 31;
    const int mw = warp >> 1, nw = warp & 1;

    for (int i = tid; i < 96*288; i += 512) { int k = i/288, n = i%288; sW[k*296+n] = __float2bfloat16(Wq[i]); }
    for (int i = tid; i < 288; i += 512) sbias[i] = bq[i];
    if (tid < 96) { sg[tid] = g1[tid]; sb[tid] = b1[tid]; }

    const uint32_t aBase = smem_u32(sA) + ((mw*16 + (lane & 15))*104 + (lane >> 4)*8) * 2;
    const uint32_t wBase = smem_u32(sW) + (((lane & 7) + ((lane >> 3) & 1)*8)*296 + (lane >> 4)*8) * 2;
    const float gg0 = g1[lane], gg1 = g1[lane+32], gg2 = g1[lane+64];
    const float bb0 = b1[lane], bb1 = b1[lane+32], bb2 = b1[lane+64];

    for (int tile = blockIdx.x; tile < NUMTILES; tile += 2*GRID) {
        if (tid < 128) stok[tid] = winrow_to_token(tile*128 + tid);
        __syncthreads();

        int tk[8];
        #pragma unroll
        for (int rr = 0; rr < 8; rr++) tk[rr] = stok[warp*8 + rr];
        float v0[8], v1[8], v2[8];
        #pragma unroll
        for (int rr = 0; rr < 8; rr++) {
            const float* xp = x + (size_t)tk[rr]*96;
            v0[rr] = __ldg(xp+lane); v1[rr] = __ldg(xp+lane+32); v2[rr] = __ldg(xp+lane+64);
        }
        #pragma unroll
        for (int rr = 0; rr < 8; rr++) {
            int r = warp*8 + rr;
            float mu = wred(v0[rr]+v1[rr]+v2[rr]) * (1.f/96.f);
            float d0 = v0[rr]-mu, d1 = v1[rr]-mu, d2 = v2[rr]-mu;
            float var = wred(d0*d0 + d1*d1 + d2*d2) * (1.f/96.f);
            float rs = rsqrtf(var + 1e-5f);
            sA[r*104+lane]    = __float2bfloat16(d0*rs*gg0 + bb0);
            sA[r*104+lane+32] = __float2bfloat16(d1*rs*gg1 + bb1);
            sA[r*104+lane+64] = __float2bfloat16(d2*rs*gg2 + bb2);
        }
        __syncthreads();

        const int r0 = tile*128 + mw*16 + (lane >> 2);
        const int cl = (lane & 3)*2;
        #pragma unroll
        for (int c = 0; c < 3; c++) {
            float acc[6][4];
            #pragma unroll
            for (int f = 0; f < 6; f++) { acc[f][0]=0.f; acc[f][1]=0.f; acc[f][2]=0.f; acc[f][3]=0.f; }
            #pragma unroll
            for (int ks = 0; ks < 6; ks++) {
                uint32_t a0,a1,a2,a3;
                ldm_x4(a0,a1,a2,a3, aBase + ks*32);
                #pragma unroll
                for (int p = 0; p < 3; p++) {
                    uint32_t b0,b1,b2,b3;
                    ldm_x4t(b0,b1,b2,b3, wBase + (ks*16*296 + c*96 + nw*48 + p*16)*2);
                    mma16816(acc[2*p],   a0,a1,a2,a3, b0,b1);
                    mma16816(acc[2*p+1], a0,a1,a2,a3, b2,b3);
                }
            }
            #pragma unroll
            for (int f = 0; f < 6; f++) {
                int col = c*96 + nw*48 + f*8 + cl;
                float bz0 = sbias[col], bz1 = sbias[col+1];
                __nv_bfloat162 p0 = __floats2bfloat162_rn(acc[f][0]+bz0, acc[f][1]+bz1);
                __nv_bfloat162 p1 = __floats2bfloat162_rn(acc[f][2]+bz0, acc[f][3]+bz1);
                *(uint32_t*)(out + (size_t)r0*288 + col)     = *(uint32_t*)&p0;
                *(uint32_t*)(out + (size_t)(r0+8)*288 + col) = *(uint32_t*)&p1;
            }
        }
    }
}

// =====================================================================
// proj kernel: raw mma + in-register LN2  [unchanged]
// =====================================================================
__global__ void __launch_bounds__(512, 1)
proj_kernel(const bf16* __restrict__ A, const float* __restrict__ Wp,
            const float* __restrict__ bp, const float* __restrict__ x,
            const float* __restrict__ g2, const float* __restrict__ b2,
            float* __restrict__ y, bf16* __restrict__ hw)
{
    extern __shared__ __align__(16) char sm[];
    bf16*  sW   = (bf16*)sm;                        // 19968
    bf16*  sA0  = (bf16*)(sm + 19968);
    bf16*  sA1  = (bf16*)(sm + 46592);
    float* rst0 = (float*)(sm + 73216);
    float* rst1 = (float*)(sm + 122368);
    int*   stok = (int*)(sm + 171520);
    float* sred = (float*)(sm + 172544);
    float* sbias= (float*)(sm + 174592);
    float* sg   = (float*)(sm + 174976);
    float* sb   = (float*)(sm + 175360);            // total 175744

    const int tid = threadIdx.x, warp = tid >> 5, lane = tid & 31;
    const int mw = warp >> 1, nw = warp & 1;
    const int t2 = (lane & 3)*2;

    for (int i = tid; i < 96*96; i += 512) { int k = i/96, n = i%96; sW[k*104+n] = __float2bfloat16(Wp[i]); }
    if (tid < 96) { sbias[tid] = bp[tid]; sg[tid] = g2[tid]; sb[tid] = b2[tid]; }

    const uint32_t wBase = smem_u32(sW) + (((lane & 7) + ((lane >> 3) & 1)*8)*104 + (lane >> 4)*8) * 2;
    const uint32_t aOff  = ((mw*16 + (lane & 15))*104 + (lane >> 4)*8) * 2;

    int tile = blockIdx.x, buf = 0;
    if (tid < 128) stok[tid] = winrow_to_token(tile*128 + tid);
    __syncthreads();
    {
        const bf16* Ag = A + (size_t)tile*128*96;
        for (int idx = tid; idx < 1536; idx += 512) { int r = idx/12, c = idx%12; cp16(sA0 + r*104 + c*8, Ag + r*96 + c*8); }
        for (int idx = tid; idx < 3072; idx += 512) { int r = idx/24, c = idx%24; cp16(rst0 + r*96 + c*4, x + (size_t)stok[r]*96 + c*4); }
    }
    CPC();

    for (; tile < NUMTILES; tile += GRID) {
        CPW(); __syncthreads();
        uint32_t aBase = smem_u32(buf ? sA1 : sA0) + aOff;
        float*   rst   = buf ? rst1 : rst0;

        int nt = tile + GRID;
        int nb = buf ^ 1;
        if (tid < 128 && nt < NUMTILES) stok[nb*128 + tid] = winrow_to_token(nt*128 + tid);
        __syncthreads();
        if (nt < NUMTILES) {
            bf16*  sAn  = nb ? sA1 : sA0;
            float* rstn = nb ? rst1 : rst0;
            const int* st = stok + nb*128;
            const bf16* Ag = A + (size_t)nt*128*96;
            for (int idx = tid; idx < 1536; idx += 512) { int r = idx/12, c = idx%12; cp16(sAn + r*104 + c*8, Ag + r*96 + c*8); }
            for (int idx = tid; idx < 3072; idx += 512) { int r = idx/24, c = idx%24; cp16(rstn + r*96 + c*4, x + (size_t)st[r]*96 + c*4); }
        }
        CPC();

        float acc[6][4];
        #pragma unroll
        for (int f = 0; f < 6; f++) { acc[f][0]=0.f; acc[f][1]=0.f; acc[f][2]=0.f; acc[f][3]=0.f; }
        #pragma unroll
        for (int ks = 0; ks < 6; ks++) {
            uint32_t a0,a1,a2,a3;
            ldm_x4(a0,a1,a2,a3, aBase + ks*32);
            #pragma unroll
            for (int p = 0; p < 3; p++) {
                uint32_t b0,b1,b2,b3;
                ldm_x4t(b0,b1,b2,b3, wBase + (ks*16*104 + nw*48 + p*16)*2);
                mma16816(acc[2*p],   a0,a1,a2,a3, b0,b1);
                mma16816(acc[2*p+1], a0,a1,a2,a3, b2,b3);
            }
        }

        #pragma unroll
        for (int g = 0; g < 2; g++) {
            int rt = mw*16 + (lane >> 2) + 8*g;
            float s = 0.f, q = 0.f;
            #pragma unroll
            for (int p = 0; p < 6; p++) {
                #pragma unroll
                for (int t = 0; t < 2; t++) {
                    int col = nw*48 + p*8 + t2 + t;
                    float v = acc[p][2*g+t] + sbias[col] + rst[rt*96 + col];
                    acc[p][2*g+t] = v;
                    s += v;  q += v*v;
                }
            }
            s += __shfl_xor_sync(0xffffffffu, s, 1);
            s += __shfl_xor_sync(0xffffffffu, s, 2);
            q += __shfl_xor_sync(0xffffffffu, q, 1);
            q += __shfl_xor_sync(0xffffffffu, q, 2);
            if ((lane & 3) == 0) { sred[rt*4 + nw*2] = s; sred[rt*4 + nw*2 + 1] = q; }
        }
        __syncthreads();

        const int* st = stok + buf*128;
        #pragma unroll
        for (int g = 0; g < 2; g++) {
            int rt = mw*16 + (lane >> 2) + 8*g;
            float S = sred[rt*4]     + sred[rt*4 + 2];
            float Q = sred[rt*4 + 1] + sred[rt*4 + 3];
            float mu = S * (1.f/96.f);
            float var = Q * (1.f/96.f) - mu*mu;
            float rs = rsqrtf(var + 1e-5f);
            int tok = st[rt];
            #pragma unroll
            for (int p = 0; p < 6; p++) {
                int col = nw*48 + p*8 + t2;
                float v0 = acc[p][2*g], v1 = acc[p][2*g+1];
                float2 yy; yy.x = v0; yy.y = v1;
                *(float2*)(y + (size_t)tok*96 + col) = yy;
                __nv_bfloat162 hh = __floats2bfloat162_rn(
                    (v0-mu)*rs*sg[col]   + sb[col],
                    (v1-mu)*rs*sg[col+1] + sb[col+1]);
                *(uint32_t*)(hw + (size_t)tok*96 + col) = *(uint32_t*)&hh;
            }
        }
        buf ^= 1;
    }
}

// =====================================================================
// fused MLP kernel: 512 threads, M=256, 16 warps; fc1 split into two
// independent 6-MMA chains (ILP 2 in the serial region); kc unroll 2
// =====================================================================
__global__ void __launch_bounds__(512, 1)
mlp_kernel(const bf16* __restrict__ A, const float* __restrict__ W1,
           const float* __restrict__ b1f, const float* __restrict__ W2,
           const float* __restrict__ b2f, float* __restrict__ y)
{
    extern __shared__ __align__(16) char sm[];
    bf16*  sW1  = (bf16*)sm;                        // 75264
    bf16*  sW2  = (bf16*)(sm + 75264);              // 79872
    bf16*  sA   = (bf16*)(sm + 155136);             // 53248
    float* sb1  = (float*)(sm + 208384);            // 1536
    float* sb2  = (float*)(sm + 209920);            // 384 (total 210304)

    const int tid = threadIdx.x, warp = tid >> 5, lane = tid & 31;

    for (int i = tid; i < 96*384; i += 512) { int k = i/384, n = i%384; sW1[k*392+n] = __float2bfloat16(W1[i]); }
    for (int i = tid; i < 384*96; i += 512) { int k = i/96,  n = i%96;  sW2[k*104+n] = __float2bfloat16(W2[i]); }
    for (int i = tid; i < 384; i += 512) sb1[i] = b1f[i];
    if (tid < 96) sb2[tid] = b2f[tid];

    const uint32_t aBase  = smem_u32(sA) + ((warp*16 + (lane & 15))*104 + (lane >> 4)*8) * 2;
    const uint32_t w1Base = smem_u32(sW1) + (((lane & 7) + ((lane >> 3) & 1)*8)*392 + (lane >> 4)*8) * 2;
    const uint32_t w2Base = smem_u32(sW2) + (((lane & 7) + ((lane >> 3) & 1)*8)*104 + (lane >> 4)*8) * 2;
    const int t2 = (lane & 3)*2;

    int tile = blockIdx.x;
    {
        const bf16* Ag = A + (size_t)tile*256*96;
        for (int idx = tid; idx < 3072; idx += 512) { int r = idx/12, c = idx%12; cp16(sA + r*104 + c*8, Ag + r*96 + c*8); }
    }
    CPC();
    __syncthreads();

    for (; tile < NUMTILES2; tile += GRID) {
        CPW(); __syncthreads();

        uint32_t areg[6][4];
        #pragma unroll
        for (int ks = 0; ks < 6; ks++)
            ldm_x4(areg[ks][0], areg[ks][1], areg[ks][2], areg[ks][3], aBase + ks*32);
        __syncthreads();

        int nt = tile + GRID;
        if (nt < NUMTILES2) {
            const bf16* Ag = A + (size_t)nt*256*96;
            for (int idx = tid; idx < 3072; idx += 512) { int r = idx/12, c = idx%12; cp16(sA + r*104 + c*8, Ag + r*96 + c*8); }
        }
        CPC();

        float acc2[12][4];
        #pragma unroll
        for (int p = 0; p < 12; p++) { acc2[p][0]=0.f; acc2[p][1]=0.f; acc2[p][2]=0.f; acc2[p][3]=0.f; }

        #pragma unroll 2
        for (int kc = 0; kc < 24; kc++) {
            // fc1: two independent 6-MMA chains (ks 0-2 -> hA, ks 3-5 -> hB)
            float hA[8], hB[8];
            #pragma unroll
            for (int i = 0; i < 8; i++) { hA[i] = 0.f; hB[i] = 0.f; }
            #pragma unroll
            for (int ks = 0; ks < 3; ks++) {
                uint32_t a0,a1,a2,a3, c0,c1,c2,c3;
                ldm_x4t(a0,a1,a2,a3, w1Base + (ks*16*392 + kc*16)*2);
                ldm_x4t(c0,c1,c2,c3, w1Base + ((ks+3)*16*392 + kc*16)*2);
                mma16816(hA,   areg[ks][0],   areg[ks][1],   areg[ks][2],   areg[ks][3],   a0,a1);
                mma16816(hB,   areg[ks+3][0], areg[ks+3][1], areg[ks+3][2], areg[ks+3][3], c0,c1);
                mma16816(hA+4, areg[ks][0],   areg[ks][1],   areg[ks][2],   areg[ks][3],   a2,a3);
                mma16816(hB+4, areg[ks+3][0], areg[ks+3][1], areg[ks+3][2], areg[ks+3][3], c2,c3);
            }
            float h[8];
            #pragma unroll
            for (int i = 0; i < 8; i++) h[i] = hA[i] + hB[i];

            int c0i = kc*16 + t2;
            float z0 = sb1[c0i], z1 = sb1[c0i+1], z8 = sb1[c0i+8], z9 = sb1[c0i+9];
            float g0 = fast_gelu(h[0]+z0), g1 = fast_gelu(h[1]+z1);
            float g2 = fast_gelu(h[2]+z0), g3 = fast_gelu(h[3]+z1);
            float g4 = fast_gelu(h[4]+z8), g5 = fast_gelu(h[5]+z9);
            float g6 = fast_gelu(h[6]+z8), g7 = fast_gelu(h[7]+z9);
            __nv_bfloat162 q0 = __floats2bfloat162_rn(g0, g1);
            __nv_bfloat162 q1 = __floats2bfloat162_rn(g2, g3);
            __nv_bfloat162 q2 = __floats2bfloat162_rn(g4, g5);
            __nv_bfloat162 q3 = __floats2bfloat162_rn(g6, g7);
            uint32_t ha0 = *(uint32_t*)&q0, ha1 = *(uint32_t*)&q1;
            uint32_t ha2 = *(uint32_t*)&q2, ha3 = *(uint32_t*)&q3;
            #pragma unroll
            for (int p = 0; p < 6; p++) {
                uint32_t b0,b1,b2,b3;
                ldm_x4t(b0,b1,b2,b3, w2Base + (kc*16*104 + p*16)*2);
                mma16816(acc2[2*p],   ha0,ha1,ha2,ha3, b0,b1);
                mma16816(acc2[2*p+1], ha0,ha1,ha2,ha3, b2,b3);
            }
        }

        const int r0 = tile*256 + warp*16 + (lane >> 2);
        #pragma unroll
        for (int p = 0; p < 12; p++) {
            int col = p*8 + t2;
            float bz0 = sb2[col], bz1 = sb2[col+1];
            float2* p0 = (float2*)(y + (size_t)r0*96 + col);
            float2* p1 = (float2*)(y + (size_t)(r0+8)*96 + col);
            float2 v0 = *p0, v1 = *p1;
            v0.x += acc2[p][0] + bz0;  v0.y += acc2[p][1] + bz1;
            v1.x += acc2[p][2] + bz0;  v1.y += acc2[p][3] + bz1;
            *p0 = v0;  *p1 = v1;
        }
    }
}

// =====================================================================
// window attention (tensor cores): Q,K 56 rows unfilled, V 64 rows
// zero-filled; 5 blocks/SM  [unchanged]
// =====================================================================
#define LDV 40
#define QKB 4480         // 56 rows x 80 B
#define HBUF 14080       // Q(4480) + K(4480) + V(5120)

__global__ void __launch_bounds__(96, 5)
attn_kernel(const bf16* __restrict__ qkv, const float* __restrict__ rpb,
            float* __restrict__ attn_w, bf16* __restrict__ outp)
{
    extern __shared__ __align__(16) char smA[];
    const int tid = threadIdx.x, warp = tid >> 5, lane = tid & 31;
    const int w = blockIdx.x, h = warp;
    char* sh = smA + warp*HBUF;
    int*   rowc = (int*)(smA + 3*HBUF);
    int*   colc = (int*)(smA + 3*HBUF + 256);
    float* srpb = (float*)(smA + 3*HBUF + 512);

    for (int i = lane; i < 75; i += 32) {
        int r = 49 + i/5, ch = i%5;
        *(uint4*)(sh + 2*QKB + (size_t)r*80 + ch*16) = make_uint4(0,0,0,0);
    }
    const bf16* base = qkv + (size_t)w*NN*288 + h*HD;
    for (int i = lane; i < 3*196; i += 32) {
        int which = i/196, rem = i%196;
        int n = rem >> 2, ch = rem & 3;
        uint4 v = *(const uint4*)(base + (size_t)n*288 + which*96 + ch*8);
        *(uint4*)(sh + which*QKB + (size_t)n*80 + ch*16) = v;
    }
    if (tid < 64) {
        int ic = tid < 49 ? tid : 48;
        int code = (ic/7)*13 + (ic%7);
        rowc[tid] = code;
        colc[tid] = 84 - code;
    }
    for (int i = tid; i < 507; i += 96) srpb[i] = rpb[(i%169)*3 + (i/169)];
    __syncthreads();

    const float* srpbh = srpb + h*169;
    const uint32_t sQu = smem_u32(sh), sKu = sQu + QKB, sVu = sQu + 2*QKB;
    const int lq = lane & 3, lr = lane >> 2;

    uint32_t kf[2][4][4];
    #pragma unroll
    for (int ks = 0; ks < 2; ks++)
        #pragma unroll
        for (int tp = 0; tp < 4; tp++)
            ldm_x4(kf[ks][tp][0], kf[ks][tp][1], kf[ks][tp][2], kf[ks][tp][3],
                   sKu + ((tp*16 + (lane&7) + ((lane>>4)&1)*8)*LDV)*2 + ((lane>>3)&1)*16 + ks*32);

    float* ap = attn_w ? attn_w + (size_t)(w*NHH + h)*(NN*NN) : (float*)0;
    const uint32_t vBase = sVu + (((lane&7) + ((lane>>3)&1)*8)*LDV + (lane>>4)*8)*2;

    #pragma unroll 1
    for (int mg = 0; mg < 2; mg++) {
        uint32_t qf[2][2][4];
        #pragma unroll
        for (int mt = 0; mt < 2; mt++)
            #pragma unroll
            for (int ks = 0; ks < 2; ks++)
                ldm_x4(qf[mt][ks][0], qf[mt][ks][1], qf[mt][ks][2], qf[mt][ks][3],
                       sQu + ((mg*32 + mt*16 + (lane&15))*LDV + (lane>>4)*8)*2 + ks*32);

        float S[2][7][4];
        #pragma unroll
        for (int mt = 0; mt < 2; mt++)
            #pragma unroll
            for (int nt = 0; nt < 7; nt++) {
                S[mt][nt][0]=0.f; S[mt][nt][1]=0.f; S[mt][nt][2]=0.f; S[mt][nt][3]=0.f;
                #pragma unroll
                for (int ks = 0; ks < 2; ks++)
                    mma16816(S[mt][nt], qf[mt][ks][0], qf[mt][ks][1], qf[mt][ks][2], qf[mt][ks][3],
                             kf[ks][nt>>1][(nt&1)*2], kf[ks][nt>>1][(nt&1)*2+1]);
            }

        float inv[2][2];
        #pragma unroll
        for (int mt = 0; mt < 2; mt++)
            #pragma unroll
            for (int g = 0; g < 2; g++) {
                int i = mg*32 + mt*16 + lr + 8*g;
                int rc = rowc[i];
                float s = 0.f;
                #pragma unroll
                for (int nt = 0; nt < 7; nt++) {
                    int j0 = nt*8 + 2*lq;
                    float b0 = srpbh[rc + colc[j0]];
                    float b1 = srpbh[rc + colc[j0+1]];
                    float e0 = (j0   < NN) ? __expf(S[mt][nt][2*g]  *SCALEV + b0) : 0.f;
                    float e1 = (j0+1 < NN) ? __expf(S[mt][nt][2*g+1]*SCALEV + b1) : 0.f;
                    S[mt][nt][2*g] = e0;  S[mt][nt][2*g+1] = e1;
                    s += e0 + e1;
                }
                s += __shfl_xor_sync(0xffffffffu, s, 1);
                s += __shfl_xor_sync(0xffffffffu, s, 2);
                inv[mt][g] = 1.f / s;
            }
        #pragma unroll
        for (int mt = 0; mt < 2; mt++)
            #pragma unroll
            for (int g = 0; g < 2; g++) {
                int i = mg*32 + mt*16 + lr + 8*g;
                float iv = inv[mt][g];
                bool rowok = (i < NN);
                #pragma unroll
                for (int nt = 0; nt < 7; nt++) {
                    int j0 = nt*8 + 2*lq;
                    float e0 = S[mt][nt][2*g]   * iv;
                    float e1 = S[mt][nt][2*g+1] * iv;
                    S[mt][nt][2*g] = e0;  S[mt][nt][2*g+1] = e1;
                    if (ap && rowok) {
                        if (j0   < NN) ap[(size_t)i*NN + j0]     = e0;
                        if (j0+1 < NN) ap[(size_t)i*NN + j0 + 1] = e1;
                    }
                }
            }

        uint32_t paf[2][4][4];
        #pragma unroll
        for (int mt = 0; mt < 2; mt++)
            #pragma unroll
            for (int t = 0; t < 4; t++) {
                __nv_bfloat162 p0 = __floats2bfloat162_rn(S[mt][2*t][0], S[mt][2*t][1]);
                __nv_bfloat162 p1 = __floats2bfloat162_rn(S[mt][2*t][2], S[mt][2*t][3]);
                paf[mt][t][0] = *(uint32_t*)&p0;
                paf[mt][t][1] = *(uint32_t*)&p1;
                if (t < 3) {
                    __nv_bfloat162 p2 = __floats2bfloat162_rn(S[mt][2*t+1][0], S[mt][2*t+1][1]);
                    __nv_bfloat162 p3 = __floats2bfloat162_rn(S[mt][2*t+1][2], S[mt][2*t+1][3]);
                    paf[mt][t][2] = *(uint32_t*)&p2;
                    paf[mt][t][3] = *(uint32_t*)&p3;
                } else {
                    paf[mt][t][2] = 0u;  paf[mt][t][3] = 0u;
                }
            }

        float O[2][4][4];
        #pragma unroll
        for (int mt = 0; mt < 2; mt++)
            #pragma unroll
            for (int p = 0; p < 4; p++) { O[mt][p][0]=0.f; O[mt][p][1]=0.f; O[mt][p][2]=0.f; O[mt][p][3]=0.f; }
        #pragma unroll
        for (int ks = 0; ks < 4; ks++) {
            uint32_t vf[2][4];
            #pragma unroll
            for (int p = 0; p < 2; p++)
                ldm_x4t(vf[p][0], vf[p][1], vf[p][2], vf[p][3],
                        vBase + (ks*16*LDV + p*16)*2);
            #pragma unroll
            for (int mt = 0; mt < 2; mt++)
                #pragma unroll
                for (int p4 = 0; p4 < 4; p4++)
                    mma16816(O[mt][p4], paf[mt][ks][0], paf[mt][ks][1], paf[mt][ks][2], paf[mt][ks][3],
                             vf[p4>>1][(p4&1)*2], vf[p4>>1][(p4&1)*2+1]);
        }

        #pragma unroll
        for (int mt = 0; mt < 2; mt++)
            #pragma unroll
            for (int g = 0; g < 2; g++) {
                int i = mg*32 + mt*16 + lr + 8*g;
                if (i < NN) {
                    bf16* op = outp + (size_t)(w*NN + i)*CC + h*HD;
                    #pragma unroll
                    for (int p4 = 0; p4 < 4; p4++) {
                        __nv_bfloat162 pk = __floats2bfloat162_rn(O[mt][p4][2*g], O[mt][p4][2*g+1]);
                        *(uint32_t*)(op + p4*8 + 2*lq) = *(uint32_t*)&pk;
                    }
                }
            }
    }
}

// ---------------- launch ----------------
extern "C" void kernel_launch(void* const* d_in, const int* in_sizes, int n_in,
                              void* d_out, int out_size) {
    const float* x      = (const float*)d_in[0];
    const float* w_qkv  = (const float*)d_in[1];
    const float* b_qkv  = (const float*)d_in[2];
    const float* w_proj = (const float*)d_in[3];
    const float* b_proj = (const float*)d_in[4];
    const float* rpb    = (const float*)d_in[5];
    const float* gamma1 = (const float*)d_in[6];
    const float* beta1  = (const float*)d_in[7];
    const float* gamma2 = (const float*)d_in[8];
    const float* beta2  = (const float*)d_in[9];
    const float* w_fc1  = (const float*)d_in[10];
    const float* b_fc1  = (const float*)d_in[11];
    const float* w_fc2  = (const float*)d_in[12];
    const float* b_fc2  = (const float*)d_in[13];

    float* y = (float*)d_out;
    float* attn_w = ((long long)out_size >= YE + AE) ? (y + YE) : (float*)0;

    bf16 *p_hw, *p_qkv, *p_att;
    cudaGetSymbolAddress((void**)&p_hw,  g_hw);
    cudaGetSymbolAddress((void**)&p_qkv, g_qkv);
    cudaGetSymbolAddress((void**)&p_att, g_att);

    const int SMQ = 85888, SMP = 175744, SMM = 210304;
    const int SMA = 3*HBUF + 512 + 507*4 + 128;   // 44908 -> 5 blocks/SM
    cudaFuncSetAttribute(qkv_kernel, cudaFuncAttributeMaxDynamicSharedMemorySize, SMQ);
    cudaFuncSetAttribute(proj_kernel, cudaFuncAttributeMaxDynamicSharedMemorySize, SMP);
    cudaFuncSetAttribute(mlp_kernel,  cudaFuncAttributeMaxDynamicSharedMemorySize, SMM);
    cudaFuncSetAttribute(attn_kernel, cudaFuncAttributeMaxDynamicSharedMemorySize, SMA);

    // 1) fused LN1 + gather + qkv GEMM (2 CTAs/SM, direct loads)
    qkv_kernel<<<2*GRID, 512, SMQ>>>(x, w_qkv, b_qkv, gamma1, beta1, p_qkv);
    // 2) window attention, tensor cores (+ attn weights), 5 blocks/SM
    attn_kernel<<<BW, 96, SMA>>>(p_qkv, rpb, attn_w, p_att);
    // 3) proj GEMM + scatter + residual + LN2 (register epilogue) -> y, hw
    proj_kernel<<<GRID, 512, SMP>>>(p_att, w_proj, b_proj, x, gamma2, beta2, y, p_hw);
    // 4) fused MLP: fc1 split-chain + GELU + fc2 + residual into y
    mlp_kernel<<<GRID, 512, SMM>>>(p_hw, w_fc1, b_fc1, w_fc2, b_fc2, y);
}

// round 16
// speedup vs baseline: 1.1339x; 1.1339x over previous
#include <cuda_runtime.h>
#include <cuda_bf16.h>
#include <math.h>
#include <stdint.h>

typedef __nv_bfloat16 bf16;

// ---------------- problem constants ----------------
#define Bc     16
#define HDIM   224
#define CC     96
#define LL     (HDIM*HDIM)
#define NTOK   (Bc*LL)              // 802816
#define WSZ    7
#define NN     49
#define NWIN   32
#define BW     (Bc*NWIN*NWIN)       // 16384
#define NHH    3
#define HD     32
#define MLPH   384
#define SHIFTV 3
#define SCALEV 0.17677669529663687f
#define NUMTILES (NTOK/128)         // 6272
#define NUMTILES2 (NTOK/256)        // 3136
#define GRID   148

static const long long YE = (long long)NTOK * CC;
static const long long AE = (long long)BW * NHH * NN * NN;

// ---------------- scratch ----------------
__device__ bf16 g_hw [(size_t)NTOK * CC];
__device__ bf16 g_qkv[(size_t)NTOK * 288];
__device__ bf16 g_att[(size_t)NTOK * CC];

// ---------------- helpers ----------------
__device__ __forceinline__ uint32_t smem_u32(const void* p) {
    uint32_t a;
    asm("{ .reg .u64 t; cvta.to.shared.u64 t, %1; cvt.u32.u64 %0, t; }" : "=r"(a) : "l"(p));
    return a;
}
__device__ __forceinline__ void cp16(void* d, const void* s) {
    asm volatile("cp.async.cg.shared.global [%0], [%1], 16;" :: "r"(smem_u32(d)), "l"(s));
}
#define CPC() asm volatile("cp.async.commit_group;" ::: "memory")
#define CPW() asm volatile("cp.async.wait_group 0;" ::: "memory")

__device__ __forceinline__ void ldm_x4(uint32_t& r0, uint32_t& r1, uint32_t& r2, uint32_t& r3, uint32_t addr) {
    asm volatile("ldmatrix.sync.aligned.m8n8.x4.shared.b16 {%0,%1,%2,%3}, [%4];"
                 : "=r"(r0), "=r"(r1), "=r"(r2), "=r"(r3) : "r"(addr));
}
__device__ __forceinline__ void ldm_x4t(uint32_t& r0, uint32_t& r1, uint32_t& r2, uint32_t& r3, uint32_t addr) {
    asm volatile("ldmatrix.sync.aligned.m8n8.x4.trans.shared.b16 {%0,%1,%2,%3}, [%4];"
                 : "=r"(r0), "=r"(r1), "=r"(r2), "=r"(r3) : "r"(addr));
}
__device__ __forceinline__ void mma16816(float* c, uint32_t a0, uint32_t a1, uint32_t a2, uint32_t a3,
                                         uint32_t b0, uint32_t b1) {
    asm volatile("mma.sync.aligned.m16n8k16.row.col.f32.bf16.bf16.f32 "
                 "{%0,%1,%2,%3}, {%4,%5,%6,%7}, {%8,%9}, {%0,%1,%2,%3};"
                 : "+f"(c[0]), "+f"(c[1]), "+f"(c[2]), "+f"(c[3])
                 : "r"(a0), "r"(a1), "r"(a2), "r"(a3), "r"(b0), "r"(b1));
}

__device__ __forceinline__ float wred(float v) {
    #pragma unroll
    for (int o = 16; o; o >>= 1) v += __shfl_xor_sync(0xffffffffu, v, o);
    return v;
}

__device__ __forceinline__ float fast_gelu(float x) {
    float t = x * (1.5957691216057308f + 0.07135481627f * x * x);
    return __fdividef(x, 1.f + __expf(-t));
}

__device__ __forceinline__ int winrow_to_token(int row) {
    int n  = row % NN;  int w = row / NN;
    int wj = w % NWIN;  int t = w / NWIN;
    int wi = t % NWIN;  int bb = t / NWIN;
    int i = n / WSZ, j = n % WSZ;
    int r = wi*WSZ + i + SHIFTV; if (r >= HDIM) r -= HDIM;
    int c = wj*WSZ + j + SHIFTV; if (c >= HDIM) c -= HDIM;
    return bb*LL + r*HDIM + c;
}

// =====================================================================
// qkv kernel: fused LN1 + gather + GEMM (96->288), 2 CTAs/SM [unchanged]
// =====================================================================
__global__ void __launch_bounds__(512, 2)
qkv_kernel(const float* __restrict__ x, const float* __restrict__ Wq,
           const float* __restrict__ bq, const float* __restrict__ g1,
           const float* __restrict__ b1, bf16* __restrict__ out)
{
    extern __shared__ __align__(16) char sm[];
    bf16*  sW   = (bf16*)sm;                       // 56832
    bf16*  sA   = (bf16*)(sm + 56832);             // 26624
    int*   stok = (int*)(sm + 83456);              // 512
    float* sbias= (float*)(sm + 83968);            // 1152
    float* sg   = (float*)(sm + 85120);            // 384
    float* sb   = (float*)(sm + 85504);            // 384  (total 85888)

    const int tid = threadIdx.x, warp = tid >> 5, lane = tid & 31;
    const int mw = warp >> 1, nw = warp & 1;

    for (int i = tid; i < 96*288; i += 512) { int k = i/288, n = i%288; sW[k*296+n] = __float2bfloat16(Wq[i]); }
    for (int i = tid; i < 288; i += 512) sbias[i] = bq[i];
    if (tid < 96) { sg[tid] = g1[tid]; sb[tid] = b1[tid]; }

    const uint32_t aBase = smem_u32(sA) + ((mw*16 + (lane & 15))*104 + (lane >> 4)*8) * 2;
    const uint32_t wBase = smem_u32(sW) + (((lane & 7) + ((lane >> 3) & 1)*8)*296 + (lane >> 4)*8) * 2;
    const float gg0 = g1[lane], gg1 = g1[lane+32], gg2 = g1[lane+64];
    const float bb0 = b1[lane], bb1 = b1[lane+32], bb2 = b1[lane+64];

    for (int tile = blockIdx.x; tile < NUMTILES; tile += 2*GRID) {
        if (tid < 128) stok[tid] = winrow_to_token(tile*128 + tid);
        __syncthreads();

        int tk[8];
        #pragma unroll
        for (int rr = 0; rr < 8; rr++) tk[rr] = stok[warp*8 + rr];
        float v0[8], v1[8], v2[8];
        #pragma unroll
        for (int rr = 0; rr < 8; rr++) {
            const float* xp = x + (size_t)tk[rr]*96;
            v0[rr] = __ldg(xp+lane); v1[rr] = __ldg(xp+lane+32); v2[rr] = __ldg(xp+lane+64);
        }
        #pragma unroll
        for (int rr = 0; rr < 8; rr++) {
            int r = warp*8 + rr;
            float mu = wred(v0[rr]+v1[rr]+v2[rr]) * (1.f/96.f);
            float d0 = v0[rr]-mu, d1 = v1[rr]-mu, d2 = v2[rr]-mu;
            float var = wred(d0*d0 + d1*d1 + d2*d2) * (1.f/96.f);
            float rs = rsqrtf(var + 1e-5f);
            sA[r*104+lane]    = __float2bfloat16(d0*rs*gg0 + bb0);
            sA[r*104+lane+32] = __float2bfloat16(d1*rs*gg1 + bb1);
            sA[r*104+lane+64] = __float2bfloat16(d2*rs*gg2 + bb2);
        }
        __syncthreads();

        const int r0 = tile*128 + mw*16 + (lane >> 2);
        const int cl = (lane & 3)*2;
        #pragma unroll
        for (int c = 0; c < 3; c++) {
            float acc[6][4];
            #pragma unroll
            for (int f = 0; f < 6; f++) { acc[f][0]=0.f; acc[f][1]=0.f; acc[f][2]=0.f; acc[f][3]=0.f; }
            #pragma unroll
            for (int ks = 0; ks < 6; ks++) {
                uint32_t a0,a1,a2,a3;
                ldm_x4(a0,a1,a2,a3, aBase + ks*32);
                #pragma unroll
                for (int p = 0; p < 3; p++) {
                    uint32_t b0,b1,b2,b3;
                    ldm_x4t(b0,b1,b2,b3, wBase + (ks*16*296 + c*96 + nw*48 + p*16)*2);
                    mma16816(acc[2*p],   a0,a1,a2,a3, b0,b1);
                    mma16816(acc[2*p+1], a0,a1,a2,a3, b2,b3);
                }
            }
            #pragma unroll
            for (int f = 0; f < 6; f++) {
                int col = c*96 + nw*48 + f*8 + cl;
                float bz0 = sbias[col], bz1 = sbias[col+1];
                __nv_bfloat162 p0 = __floats2bfloat162_rn(acc[f][0]+bz0, acc[f][1]+bz1);
                __nv_bfloat162 p1 = __floats2bfloat162_rn(acc[f][2]+bz0, acc[f][3]+bz1);
                *(uint32_t*)(out + (size_t)r0*288 + col)     = *(uint32_t*)&p0;
                *(uint32_t*)(out + (size_t)(r0+8)*288 + col) = *(uint32_t*)&p1;
            }
        }
    }
}

// =====================================================================
// proj kernel: raw mma + in-register LN2  [unchanged]
// =====================================================================
__global__ void __launch_bounds__(512, 1)
proj_kernel(const bf16* __restrict__ A, const float* __restrict__ Wp,
            const float* __restrict__ bp, const float* __restrict__ x,
            const float* __restrict__ g2, const float* __restrict__ b2,
            float* __restrict__ y, bf16* __restrict__ hw)
{
    extern __shared__ __align__(16) char sm[];
    bf16*  sW   = (bf16*)sm;                        // 19968
    bf16*  sA0  = (bf16*)(sm + 19968);
    bf16*  sA1  = (bf16*)(sm + 46592);
    float* rst0 = (float*)(sm + 73216);
    float* rst1 = (float*)(sm + 122368);
    int*   stok = (int*)(sm + 171520);
    float* sred = (float*)(sm + 172544);
    float* sbias= (float*)(sm + 174592);
    float* sg   = (float*)(sm + 174976);
    float* sb   = (float*)(sm + 175360);            // total 175744

    const int tid = threadIdx.x, warp = tid >> 5, lane = tid & 31;
    const int mw = warp >> 1, nw = warp & 1;
    const int t2 = (lane & 3)*2;

    for (int i = tid; i < 96*96; i += 512) { int k = i/96, n = i%96; sW[k*104+n] = __float2bfloat16(Wp[i]); }
    if (tid < 96) { sbias[tid] = bp[tid]; sg[tid] = g2[tid]; sb[tid] = b2[tid]; }

    const uint32_t wBase = smem_u32(sW) + (((lane & 7) + ((lane >> 3) & 1)*8)*104 + (lane >> 4)*8) * 2;
    const uint32_t aOff  = ((mw*16 + (lane & 15))*104 + (lane >> 4)*8) * 2;

    int tile = blockIdx.x, buf = 0;
    if (tid < 128) stok[tid] = winrow_to_token(tile*128 + tid);
    __syncthreads();
    {
        const bf16* Ag = A + (size_t)tile*128*96;
        for (int idx = tid; idx < 1536; idx += 512) { int r = idx/12, c = idx%12; cp16(sA0 + r*104 + c*8, Ag + r*96 + c*8); }
        for (int idx = tid; idx < 3072; idx += 512) { int r = idx/24, c = idx%24; cp16(rst0 + r*96 + c*4, x + (size_t)stok[r]*96 + c*4); }
    }
    CPC();

    for (; tile < NUMTILES; tile += GRID) {
        CPW(); __syncthreads();
        uint32_t aBase = smem_u32(buf ? sA1 : sA0) + aOff;
        float*   rst   = buf ? rst1 : rst0;

        int nt = tile + GRID;
        int nb = buf ^ 1;
        if (tid < 128 && nt < NUMTILES) stok[nb*128 + tid] = winrow_to_token(nt*128 + tid);
        __syncthreads();
        if (nt < NUMTILES) {
            bf16*  sAn  = nb ? sA1 : sA0;
            float* rstn = nb ? rst1 : rst0;
            const int* st = stok + nb*128;
            const bf16* Ag = A + (size_t)nt*128*96;
            for (int idx = tid; idx < 1536; idx += 512) { int r = idx/12, c = idx%12; cp16(sAn + r*104 + c*8, Ag + r*96 + c*8); }
            for (int idx = tid; idx < 3072; idx += 512) { int r = idx/24, c = idx%24; cp16(rstn + r*96 + c*4, x + (size_t)st[r]*96 + c*4); }
        }
        CPC();

        float acc[6][4];
        #pragma unroll
        for (int f = 0; f < 6; f++) { acc[f][0]=0.f; acc[f][1]=0.f; acc[f][2]=0.f; acc[f][3]=0.f; }
        #pragma unroll
        for (int ks = 0; ks < 6; ks++) {
            uint32_t a0,a1,a2,a3;
            ldm_x4(a0,a1,a2,a3, aBase + ks*32);
            #pragma unroll
            for (int p = 0; p < 3; p++) {
                uint32_t b0,b1,b2,b3;
                ldm_x4t(b0,b1,b2,b3, wBase + (ks*16*104 + nw*48 + p*16)*2);
                mma16816(acc[2*p],   a0,a1,a2,a3, b0,b1);
                mma16816(acc[2*p+1], a0,a1,a2,a3, b2,b3);
            }
        }

        #pragma unroll
        for (int g = 0; g < 2; g++) {
            int rt = mw*16 + (lane >> 2) + 8*g;
            float s = 0.f, q = 0.f;
            #pragma unroll
            for (int p = 0; p < 6; p++) {
                #pragma unroll
                for (int t = 0; t < 2; t++) {
                    int col = nw*48 + p*8 + t2 + t;
                    float v = acc[p][2*g+t] + sbias[col] + rst[rt*96 + col];
                    acc[p][2*g+t] = v;
                    s += v;  q += v*v;
                }
            }
            s += __shfl_xor_sync(0xffffffffu, s, 1);
            s += __shfl_xor_sync(0xffffffffu, s, 2);
            q += __shfl_xor_sync(0xffffffffu, q, 1);
            q += __shfl_xor_sync(0xffffffffu, q, 2);
            if ((lane & 3) == 0) { sred[rt*4 + nw*2] = s; sred[rt*4 + nw*2 + 1] = q; }
        }
        __syncthreads();

        const int* st = stok + buf*128;
        #pragma unroll
        for (int g = 0; g < 2; g++) {
            int rt = mw*16 + (lane >> 2) + 8*g;
            float S = sred[rt*4]     + sred[rt*4 + 2];
            float Q = sred[rt*4 + 1] + sred[rt*4 + 3];
            float mu = S * (1.f/96.f);
            float var = Q * (1.f/96.f) - mu*mu;
            float rs = rsqrtf(var + 1e-5f);
            int tok = st[rt];
            #pragma unroll
            for (int p = 0; p < 6; p++) {
                int col = nw*48 + p*8 + t2;
                float v0 = acc[p][2*g], v1 = acc[p][2*g+1];
                float2 yy; yy.x = v0; yy.y = v1;
                *(float2*)(y + (size_t)tok*96 + col) = yy;
                __nv_bfloat162 hh = __floats2bfloat162_rn(
                    (v0-mu)*rs*sg[col]   + sb[col],
                    (v1-mu)*rs*sg[col+1] + sb[col+1]);
                *(uint32_t*)(hw + (size_t)tok*96 + col) = *(uint32_t*)&hh;
            }
        }
        buf ^= 1;
    }
}

// =====================================================================
// fused MLP kernel [R14-exact structure]: 512 threads, M=256, 16 warps,
// kc unroll 2; gelu uses __fdividef (fast rcp instead of IEEE div)
// =====================================================================
__global__ void __launch_bounds__(512, 1)
mlp_kernel(const bf16* __restrict__ A, const float* __restrict__ W1,
           const float* __restrict__ b1f, const float* __restrict__ W2,
           const float* __restrict__ b2f, float* __restrict__ y)
{
    extern __shared__ __align__(16) char sm[];
    bf16*  sW1  = (bf16*)sm;                        // 75264
    bf16*  sW2  = (bf16*)(sm + 75264);              // 79872
    bf16*  sA   = (bf16*)(sm + 155136);             // 53248
    float* sb1  = (float*)(sm + 208384);            // 1536
    float* sb2  = (float*)(sm + 209920);            // 384 (total 210304)

    const int tid = threadIdx.x, warp = tid >> 5, lane = tid & 31;

    for (int i = tid; i < 96*384; i += 512) { int k = i/384, n = i%384; sW1[k*392+n] = __float2bfloat16(W1[i]); }
    for (int i = tid; i < 384*96; i += 512) { int k = i/96,  n = i%96;  sW2[k*104+n] = __float2bfloat16(W2[i]); }
    for (int i = tid; i < 384; i += 512) sb1[i] = b1f[i];
    if (tid < 96) sb2[tid] = b2f[tid];

    const uint32_t aBase  = smem_u32(sA) + ((warp*16 + (lane & 15))*104 + (lane >> 4)*8) * 2;
    const uint32_t w1Base = smem_u32(sW1) + (((lane & 7) + ((lane >> 3) & 1)*8)*392 + (lane >> 4)*8) * 2;
    const uint32_t w2Base = smem_u32(sW2) + (((lane & 7) + ((lane >> 3) & 1)*8)*104 + (lane >> 4)*8) * 2;
    const int t2 = (lane & 3)*2;

    int tile = blockIdx.x;
    {
        const bf16* Ag = A + (size_t)tile*256*96;
        for (int idx = tid; idx < 3072; idx += 512) { int r = idx/12, c = idx%12; cp16(sA + r*104 + c*8, Ag + r*96 + c*8); }
    }
    CPC();
    __syncthreads();

    for (; tile < NUMTILES2; tile += GRID) {
        CPW(); __syncthreads();

        uint32_t areg[6][4];
        #pragma unroll
        for (int ks = 0; ks < 6; ks++)
            ldm_x4(areg[ks][0], areg[ks][1], areg[ks][2], areg[ks][3], aBase + ks*32);
        __syncthreads();

        int nt = tile + GRID;
        if (nt < NUMTILES2) {
            const bf16* Ag = A + (size_t)nt*256*96;
            for (int idx = tid; idx < 3072; idx += 512) { int r = idx/12, c = idx%12; cp16(sA + r*104 + c*8, Ag + r*96 + c*8); }
        }
        CPC();

        float acc2[12][4];
        #pragma unroll
        for (int p = 0; p < 12; p++) { acc2[p][0]=0.f; acc2[p][1]=0.f; acc2[p][2]=0.f; acc2[p][3]=0.f; }

        #pragma unroll 2
        for (int kc = 0; kc < 24; kc++) {
            float h[8];
            #pragma unroll
            for (int i = 0; i < 8; i++) h[i] = 0.f;
            #pragma unroll
            for (int ks = 0; ks < 6; ks++) {
                uint32_t b0,b1,b2,b3;
                ldm_x4t(b0,b1,b2,b3, w1Base + (ks*16*392 + kc*16)*2);
                mma16816(h,   areg[ks][0], areg[ks][1], areg[ks][2], areg[ks][3], b0,b1);
                mma16816(h+4, areg[ks][0], areg[ks][1], areg[ks][2], areg[ks][3], b2,b3);
            }
            int c0 = kc*16 + t2;
            float z0 = sb1[c0], z1 = sb1[c0+1], z8 = sb1[c0+8], z9 = sb1[c0+9];
            float g0 = fast_gelu(h[0]+z0), g1 = fast_gelu(h[1]+z1);
            float g2 = fast_gelu(h[2]+z0), g3 = fast_gelu(h[3]+z1);
            float g4 = fast_gelu(h[4]+z8), g5 = fast_gelu(h[5]+z9);
            float g6 = fast_gelu(h[6]+z8), g7 = fast_gelu(h[7]+z9);
            __nv_bfloat162 q0 = __floats2bfloat162_rn(g0, g1);
            __nv_bfloat162 q1 = __floats2bfloat162_rn(g2, g3);
            __nv_bfloat162 q2 = __floats2bfloat162_rn(g4, g5);
            __nv_bfloat162 q3 = __floats2bfloat162_rn(g6, g7);
            uint32_t ha0 = *(uint32_t*)&q0, ha1 = *(uint32_t*)&q1;
            uint32_t ha2 = *(uint32_t*)&q2, ha3 = *(uint32_t*)&q3;
            #pragma unroll
            for (int p = 0; p < 6; p++) {
                uint32_t b0,b1,b2,b3;
                ldm_x4t(b0,b1,b2,b3, w2Base + (kc*16*104 + p*16)*2);
                mma16816(acc2[2*p],   ha0,ha1,ha2,ha3, b0,b1);
                mma16816(acc2[2*p+1], ha0,ha1,ha2,ha3, b2,b3);
            }
        }

        const int r0 = tile*256 + warp*16 + (lane >> 2);
        #pragma unroll
        for (int p = 0; p < 12; p++) {
            int col = p*8 + t2;
            float bz0 = sb2[col], bz1 = sb2[col+1];
            float2* p0 = (float2*)(y + (size_t)r0*96 + col);
            float2* p1 = (float2*)(y + (size_t)(r0+8)*96 + col);
            float2 v0 = *p0, v1 = *p1;
            v0.x += acc2[p][0] + bz0;  v0.y += acc2[p][1] + bz1;
            v1.x += acc2[p][2] + bz0;  v1.y += acc2[p][3] + bz1;
            *p0 = v0;  *p1 = v1;
        }
    }
}

// =====================================================================
// window attention (tensor cores): Q,K 56 rows unfilled, V 64 rows
// zero-filled; 5 blocks/SM  [unchanged]
// =====================================================================
#define LDV 40
#define QKB 4480         // 56 rows x 80 B
#define HBUF 14080       // Q(4480) + K(4480) + V(5120)

__global__ void __launch_bounds__(96, 5)
attn_kernel(const bf16* __restrict__ qkv, const float* __restrict__ rpb,
            float* __restrict__ attn_w, bf16* __restrict__ outp)
{
    extern __shared__ __align__(16) char smA[];
    const int tid = threadIdx.x, warp = tid >> 5, lane = tid & 31;
    const int w = blockIdx.x, h = warp;
    char* sh = smA + warp*HBUF;
    int*   rowc = (int*)(smA + 3*HBUF);
    int*   colc = (int*)(smA + 3*HBUF + 256);
    float* srpb = (float*)(smA + 3*HBUF + 512);

    for (int i = lane; i < 75; i += 32) {
        int r = 49 + i/5, ch = i%5;
        *(uint4*)(sh + 2*QKB + (size_t)r*80 + ch*16) = make_uint4(0,0,0,0);
    }
    const bf16* base = qkv + (size_t)w*NN*288 + h*HD;
    for (int i = lane; i < 3*196; i += 32) {
        int which = i/196, rem = i%196;
        int n = rem >> 2, ch = rem & 3;
        uint4 v = *(const uint4*)(base + (size_t)n*288 + which*96 + ch*8);
        *(uint4*)(sh + which*QKB + (size_t)n*80 + ch*16) = v;
    }
    if (tid < 64) {
        int ic = tid < 49 ? tid : 48;
        int code = (ic/7)*13 + (ic%7);
        rowc[tid] = code;
        colc[tid] = 84 - code;
    }
    for (int i = tid; i < 507; i += 96) srpb[i] = rpb[(i%169)*3 + (i/169)];
    __syncthreads();

    const float* srpbh = srpb + h*169;
    const uint32_t sQu = smem_u32(sh), sKu = sQu + QKB, sVu = sQu + 2*QKB;
    const int lq = lane & 3, lr = lane >> 2;

    uint32_t kf[2][4][4];
    #pragma unroll
    for (int ks = 0; ks < 2; ks++)
        #pragma unroll
        for (int tp = 0; tp < 4; tp++)
            ldm_x4(kf[ks][tp][0], kf[ks][tp][1], kf[ks][tp][2], kf[ks][tp][3],
                   sKu + ((tp*16 + (lane&7) + ((lane>>4)&1)*8)*LDV)*2 + ((lane>>3)&1)*16 + ks*32);

    float* ap = attn_w ? attn_w + (size_t)(w*NHH + h)*(NN*NN) : (float*)0;
    const uint32_t vBase = sVu + (((lane&7) + ((lane>>3)&1)*8)*LDV + (lane>>4)*8)*2;

    #pragma unroll 1
    for (int mg = 0; mg < 2; mg++) {
        uint32_t qf[2][2][4];
        #pragma unroll
        for (int mt = 0; mt < 2; mt++)
            #pragma unroll
            for (int ks = 0; ks < 2; ks++)
                ldm_x4(qf[mt][ks][0], qf[mt][ks][1], qf[mt][ks][2], qf[mt][ks][3],
                       sQu + ((mg*32 + mt*16 + (lane&15))*LDV + (lane>>4)*8)*2 + ks*32);

        float S[2][7][4];
        #pragma unroll
        for (int mt = 0; mt < 2; mt++)
            #pragma unroll
            for (int nt = 0; nt < 7; nt++) {
                S[mt][nt][0]=0.f; S[mt][nt][1]=0.f; S[mt][nt][2]=0.f; S[mt][nt][3]=0.f;
                #pragma unroll
                for (int ks = 0; ks < 2; ks++)
                    mma16816(S[mt][nt], qf[mt][ks][0], qf[mt][ks][1], qf[mt][ks][2], qf[mt][ks][3],
                             kf[ks][nt>>1][(nt&1)*2], kf[ks][nt>>1][(nt&1)*2+1]);
            }

        float inv[2][2];
        #pragma unroll
        for (int mt = 0; mt < 2; mt++)
            #pragma unroll
            for (int g = 0; g < 2; g++) {
                int i = mg*32 + mt*16 + lr + 8*g;
                int rc = rowc[i];
                float s = 0.f;
                #pragma unroll
                for (int nt = 0; nt < 7; nt++) {
                    int j0 = nt*8 + 2*lq;
                    float b0 = srpbh[rc + colc[j0]];
                    float b1 = srpbh[rc + colc[j0+1]];
                    float e0 = (j0   < NN) ? __expf(S[mt][nt][2*g]  *SCALEV + b0) : 0.f;
                    float e1 = (j0+1 < NN) ? __expf(S[mt][nt][2*g+1]*SCALEV + b1) : 0.f;
                    S[mt][nt][2*g] = e0;  S[mt][nt][2*g+1] = e1;
                    s += e0 + e1;
                }
                s += __shfl_xor_sync(0xffffffffu, s, 1);
                s += __shfl_xor_sync(0xffffffffu, s, 2);
                inv[mt][g] = 1.f / s;
            }
        #pragma unroll
        for (int mt = 0; mt < 2; mt++)
            #pragma unroll
            for (int g = 0; g < 2; g++) {
                int i = mg*32 + mt*16 + lr + 8*g;
                float iv = inv[mt][g];
                bool rowok = (i < NN);
                #pragma unroll
                for (int nt = 0; nt < 7; nt++) {
                    int j0 = nt*8 + 2*lq;
                    float e0 = S[mt][nt][2*g]   * iv;
                    float e1 = S[mt][nt][2*g+1] * iv;
                    S[mt][nt][2*g] = e0;  S[mt][nt][2*g+1] = e1;
                    if (ap && rowok) {
                        if (j0   < NN) ap[(size_t)i*NN + j0]     = e0;
                        if (j0+1 < NN) ap[(size_t)i*NN + j0 + 1] = e1;
                    }
                }
            }

        uint32_t paf[2][4][4];
        #pragma unroll
        for (int mt = 0; mt < 2; mt++)
            #pragma unroll
            for (int t = 0; t < 4; t++) {
                __nv_bfloat162 p0 = __floats2bfloat162_rn(S[mt][2*t][0], S[mt][2*t][1]);
                __nv_bfloat162 p1 = __floats2bfloat162_rn(S[mt][2*t][2], S[mt][2*t][3]);
                paf[mt][t][0] = *(uint32_t*)&p0;
                paf[mt][t][1] = *(uint32_t*)&p1;
                if (t < 3) {
                    __nv_bfloat162 p2 = __floats2bfloat162_rn(S[mt][2*t+1][0], S[mt][2*t+1][1]);
                    __nv_bfloat162 p3 = __floats2bfloat162_rn(S[mt][2*t+1][2], S[mt][2*t+1][3]);
                    paf[mt][t][2] = *(uint32_t*)&p2;
                    paf[mt][t][3] = *(uint32_t*)&p3;
                } else {
                    paf[mt][t][2] = 0u;  paf[mt][t][3] = 0u;
                }
            }

        float O[2][4][4];
        #pragma unroll
        for (int mt = 0; mt < 2; mt++)
            #pragma unroll
            for (int p = 0; p < 4; p++) { O[mt][p][0]=0.f; O[mt][p][1]=0.f; O[mt][p][2]=0.f; O[mt][p][3]=0.f; }
        #pragma unroll
        for (int ks = 0; ks < 4; ks++) {
            uint32_t vf[2][4];
            #pragma unroll
            for (int p = 0; p < 2; p++)
                ldm_x4t(vf[p][0], vf[p][1], vf[p][2], vf[p][3],
                        vBase + (ks*16*LDV + p*16)*2);
            #pragma unroll
            for (int mt = 0; mt < 2; mt++)
                #pragma unroll
                for (int p4 = 0; p4 < 4; p4++)
                    mma16816(O[mt][p4], paf[mt][ks][0], paf[mt][ks][1], paf[mt][ks][2], paf[mt][ks][3],
                             vf[p4>>1][(p4&1)*2], vf[p4>>1][(p4&1)*2+1]);
        }

        #pragma unroll
        for (int mt = 0; mt < 2; mt++)
            #pragma unroll
            for (int g = 0; g < 2; g++) {
                int i = mg*32 + mt*16 + lr + 8*g;
                if (i < NN) {
                    bf16* op = outp + (size_t)(w*NN + i)*CC + h*HD;
                    #pragma unroll
                    for (int p4 = 0; p4 < 4; p4++) {
                        __nv_bfloat162 pk = __floats2bfloat162_rn(O[mt][p4][2*g], O[mt][p4][2*g+1]);
                        *(uint32_t*)(op + p4*8 + 2*lq) = *(uint32_t*)&pk;
                    }
                }
            }
    }
}

// ---------------- launch ----------------
extern "C" void kernel_launch(void* const* d_in, const int* in_sizes, int n_in,
                              void* d_out, int out_size) {
    const float* x      = (const float*)d_in[0];
    const float* w_qkv  = (const float*)d_in[1];
    const float* b_qkv  = (const float*)d_in[2];
    const float* w_proj = (const float*)d_in[3];
    const float* b_proj = (const float*)d_in[4];
    const float* rpb    = (const float*)d_in[5];
    const float* gamma1 = (const float*)d_in[6];
    const float* beta1  = (const float*)d_in[7];
    const float* gamma2 = (const float*)d_in[8];
    const float* beta2  = (const float*)d_in[9];
    const float* w_fc1  = (const float*)d_in[10];
    const float* b_fc1  = (const float*)d_in[11];
    const float* w_fc2  = (const float*)d_in[12];
    const float* b_fc2  = (const float*)d_in[13];

    float* y = (float*)d_out;
    float* attn_w = ((long long)out_size >= YE + AE) ? (y + YE) : (float*)0;

    bf16 *p_hw, *p_qkv, *p_att;
    cudaGetSymbolAddress((void**)&p_hw,  g_hw);
    cudaGetSymbolAddress((void**)&p_qkv, g_qkv);
    cudaGetSymbolAddress((void**)&p_att, g_att);

    const int SMQ = 85888, SMP = 175744, SMM = 210304;
    const int SMA = 3*HBUF + 512 + 507*4 + 128;   // 44908 -> 5 blocks/SM
    cudaFuncSetAttribute(qkv_kernel, cudaFuncAttributeMaxDynamicSharedMemorySize, SMQ);
    cudaFuncSetAttribute(proj_kernel, cudaFuncAttributeMaxDynamicSharedMemorySize, SMP);
    cudaFuncSetAttribute(mlp_kernel,  cudaFuncAttributeMaxDynamicSharedMemorySize, SMM);
    cudaFuncSetAttribute(attn_kernel, cudaFuncAttributeMaxDynamicSharedMemorySize, SMA);

    // 1) fused LN1 + gather + qkv GEMM (2 CTAs/SM, direct loads)
    qkv_kernel<<<2*GRID, 512, SMQ>>>(x, w_qkv, b_qkv, gamma1, beta1, p_qkv);
    // 2) window attention, tensor cores (+ attn weights), 5 blocks/SM
    attn_kernel<<<BW, 96, SMA>>>(p_qkv, rpb, attn_w, p_att);
    // 3) proj GEMM + scatter + residual + LN2 (register epilogue) -> y, hw
    proj_kernel<<<GRID, 512, SMP>>>(p_att, w_proj, b_proj, x, gamma2, beta2, y, p_hw);
    // 4) fused MLP: fc1 + GELU(fast div) + fc2 + residual into y
    mlp_kernel<<<GRID, 512, SMM>>>(p_hw, w_fc1, b_fc1, w_fc2, b_fc2, y);
}

// round 17
// speedup vs baseline: 1.1389x; 1.0045x over previous
#include <cuda_runtime.h>
#include <cuda_bf16.h>
#include <math.h>
#include <stdint.h>

typedef __nv_bfloat16 bf16;

// ---------------- problem constants ----------------
#define Bc     16
#define HDIM   224
#define CC     96
#define LL     (HDIM*HDIM)
#define NTOK   (Bc*LL)              // 802816
#define WSZ    7
#define NN     49
#define NWIN   32
#define BW     (Bc*NWIN*NWIN)       // 16384
#define NHH    3
#define HD     32
#define MLPH   384
#define SHIFTV 3
#define SCALEV 0.17677669529663687f
#define NUMTILES (NTOK/128)         // 6272
#define NUMTILES2 (NTOK/256)        // 3136
#define GRID   148

static const long long YE = (long long)NTOK * CC;
static const long long AE = (long long)BW * NHH * NN * NN;

// ---------------- scratch ----------------
__device__ bf16 g_hw [(size_t)NTOK * CC];
__device__ bf16 g_qkv[(size_t)NTOK * 288];
__device__ bf16 g_att[(size_t)NTOK * CC];

// ---------------- helpers ----------------
__device__ __forceinline__ uint32_t smem_u32(const void* p) {
    uint32_t a;
    asm("{ .reg .u64 t; cvta.to.shared.u64 t, %1; cvt.u32.u64 %0, t; }" : "=r"(a) : "l"(p));
    return a;
}
__device__ __forceinline__ void cp16(void* d, const void* s) {
    asm volatile("cp.async.cg.shared.global [%0], [%1], 16;" :: "r"(smem_u32(d)), "l"(s));
}
#define CPC() asm volatile("cp.async.commit_group;" ::: "memory")
#define CPW() asm volatile("cp.async.wait_group 0;" ::: "memory")

__device__ __forceinline__ void ldm_x4(uint32_t& r0, uint32_t& r1, uint32_t& r2, uint32_t& r3, uint32_t addr) {
    asm volatile("ldmatrix.sync.aligned.m8n8.x4.shared.b16 {%0,%1,%2,%3}, [%4];"
                 : "=r"(r0), "=r"(r1), "=r"(r2), "=r"(r3) : "r"(addr));
}
__device__ __forceinline__ void ldm_x4t(uint32_t& r0, uint32_t& r1, uint32_t& r2, uint32_t& r3, uint32_t addr) {
    asm volatile("ldmatrix.sync.aligned.m8n8.x4.trans.shared.b16 {%0,%1,%2,%3}, [%4];"
                 : "=r"(r0), "=r"(r1), "=r"(r2), "=r"(r3) : "r"(addr));
}
__device__ __forceinline__ void mma16816(float* c, uint32_t a0, uint32_t a1, uint32_t a2, uint32_t a3,
                                         uint32_t b0, uint32_t b1) {
    asm volatile("mma.sync.aligned.m16n8k16.row.col.f32.bf16.bf16.f32 "
                 "{%0,%1,%2,%3}, {%4,%5,%6,%7}, {%8,%9}, {%0,%1,%2,%3};"
                 : "+f"(c[0]), "+f"(c[1]), "+f"(c[2]), "+f"(c[3])
                 : "r"(a0), "r"(a1), "r"(a2), "r"(a3), "r"(b0), "r"(b1));
}

__device__ __forceinline__ float wred(float v) {
    #pragma unroll
    for (int o = 16; o; o >>= 1) v += __shfl_xor_sync(0xffffffffu, v, o);
    return v;
}

__device__ __forceinline__ float fast_gelu(float x) {
    float t = x * (1.5957691216057308f + 0.07135481627f * x * x);
    return __fdividef(x, 1.f + __expf(-t));
}

__device__ __forceinline__ int winrow_to_token(int row) {
    int n  = row % NN;  int w = row / NN;
    int wj = w % NWIN;  int t = w / NWIN;
    int wi = t % NWIN;  int bb = t / NWIN;
    int i = n / WSZ, j = n % WSZ;
    int r = wi*WSZ + i + SHIFTV; if (r >= HDIM) r -= HDIM;
    int c = wj*WSZ + j + SHIFTV; if (c >= HDIM) c -= HDIM;
    return bb*LL + r*HDIM + c;
}

// =====================================================================
// qkv kernel: fused LN1 + gather + GEMM (96->288), 2 CTAs/SM [unchanged]
// =====================================================================
__global__ void __launch_bounds__(512, 2)
qkv_kernel(const float* __restrict__ x, const float* __restrict__ Wq,
           const float* __restrict__ bq, const float* __restrict__ g1,
           const float* __restrict__ b1, bf16* __restrict__ out)
{
    extern __shared__ __align__(16) char sm[];
    bf16*  sW   = (bf16*)sm;                       // 56832
    bf16*  sA   = (bf16*)(sm + 56832);             // 26624
    int*   stok = (int*)(sm + 83456);              // 512
    float* sbias= (float*)(sm + 83968);            // 1152
    float* sg   = (float*)(sm + 85120);            // 384
    float* sb   = (float*)(sm + 85504);            // 384  (total 85888)

    const int tid = threadIdx.x, warp = tid >> 5, lane = tid & 31;
    const int mw = warp >> 1, nw = warp & 1;

    for (int i = tid; i < 96*288; i += 512) { int k = i/288, n = i%288; sW[k*296+n] = __float2bfloat16(Wq[i]); }
    for (int i = tid; i < 288; i += 512) sbias[i] = bq[i];
    if (tid < 96) { sg[tid] = g1[tid]; sb[tid] = b1[tid]; }

    const uint32_t aBase = smem_u32(sA) + ((mw*16 + (lane & 15))*104 + (lane >> 4)*8) * 2;
    const uint32_t wBase = smem_u32(sW) + (((lane & 7) + ((lane >> 3) & 1)*8)*296 + (lane >> 4)*8) * 2;
    const float gg0 = g1[lane], gg1 = g1[lane+32], gg2 = g1[lane+64];
    const float bb0 = b1[lane], bb1 = b1[lane+32], bb2 = b1[lane+64];

    for (int tile = blockIdx.x; tile < NUMTILES; tile += 2*GRID) {
        if (tid < 128) stok[tid] = winrow_to_token(tile*128 + tid);
        __syncthreads();

        int tk[8];
        #pragma unroll
        for (int rr = 0; rr < 8; rr++) tk[rr] = stok[warp*8 + rr];
        float v0[8], v1[8], v2[8];
        #pragma unroll
        for (int rr = 0; rr < 8; rr++) {
            const float* xp = x + (size_t)tk[rr]*96;
            v0[rr] = __ldg(xp+lane); v1[rr] = __ldg(xp+lane+32); v2[rr] = __ldg(xp+lane+64);
        }
        #pragma unroll
        for (int rr = 0; rr < 8; rr++) {
            int r = warp*8 + rr;
            float mu = wred(v0[rr]+v1[rr]+v2[rr]) * (1.f/96.f);
            float d0 = v0[rr]-mu, d1 = v1[rr]-mu, d2 = v2[rr]-mu;
            float var = wred(d0*d0 + d1*d1 + d2*d2) * (1.f/96.f);
            float rs = rsqrtf(var + 1e-5f);
            sA[r*104+lane]    = __float2bfloat16(d0*rs*gg0 + bb0);
            sA[r*104+lane+32] = __float2bfloat16(d1*rs*gg1 + bb1);
            sA[r*104+lane+64] = __float2bfloat16(d2*rs*gg2 + bb2);
        }
        __syncthreads();

        const int r0 = tile*128 + mw*16 + (lane >> 2);
        const int cl = (lane & 3)*2;
        #pragma unroll
        for (int c = 0; c < 3; c++) {
            float acc[6][4];
            #pragma unroll
            for (int f = 0; f < 6; f++) { acc[f][0]=0.f; acc[f][1]=0.f; acc[f][2]=0.f; acc[f][3]=0.f; }
            #pragma unroll
            for (int ks = 0; ks < 6; ks++) {
                uint32_t a0,a1,a2,a3;
                ldm_x4(a0,a1,a2,a3, aBase + ks*32);
                #pragma unroll
                for (int p = 0; p < 3; p++) {
                    uint32_t b0,b1,b2,b3;
                    ldm_x4t(b0,b1,b2,b3, wBase + (ks*16*296 + c*96 + nw*48 + p*16)*2);
                    mma16816(acc[2*p],   a0,a1,a2,a3, b0,b1);
                    mma16816(acc[2*p+1], a0,a1,a2,a3, b2,b3);
                }
            }
            #pragma unroll
            for (int f = 0; f < 6; f++) {
                int col = c*96 + nw*48 + f*8 + cl;
                float bz0 = sbias[col], bz1 = sbias[col+1];
                __nv_bfloat162 p0 = __floats2bfloat162_rn(acc[f][0]+bz0, acc[f][1]+bz1);
                __nv_bfloat162 p1 = __floats2bfloat162_rn(acc[f][2]+bz0, acc[f][3]+bz1);
                *(uint32_t*)(out + (size_t)r0*288 + col)     = *(uint32_t*)&p0;
                *(uint32_t*)(out + (size_t)(r0+8)*288 + col) = *(uint32_t*)&p1;
            }
        }
    }
}

// =====================================================================
// proj kernel: raw mma + in-register LN2  [unchanged]
// =====================================================================
__global__ void __launch_bounds__(512, 1)
proj_kernel(const bf16* __restrict__ A, const float* __restrict__ Wp,
            const float* __restrict__ bp, const float* __restrict__ x,
            const float* __restrict__ g2, const float* __restrict__ b2,
            float* __restrict__ y, bf16* __restrict__ hw)
{
    extern __shared__ __align__(16) char sm[];
    bf16*  sW   = (bf16*)sm;                        // 19968
    bf16*  sA0  = (bf16*)(sm + 19968);
    bf16*  sA1  = (bf16*)(sm + 46592);
    float* rst0 = (float*)(sm + 73216);
    float* rst1 = (float*)(sm + 122368);
    int*   stok = (int*)(sm + 171520);
    float* sred = (float*)(sm + 172544);
    float* sbias= (float*)(sm + 174592);
    float* sg   = (float*)(sm + 174976);
    float* sb   = (float*)(sm + 175360);            // total 175744

    const int tid = threadIdx.x, warp = tid >> 5, lane = tid & 31;
    const int mw = warp >> 1, nw = warp & 1;
    const int t2 = (lane & 3)*2;

    for (int i = tid; i < 96*96; i += 512) { int k = i/96, n = i%96; sW[k*104+n] = __float2bfloat16(Wp[i]); }
    if (tid < 96) { sbias[tid] = bp[tid]; sg[tid] = g2[tid]; sb[tid] = b2[tid]; }

    const uint32_t wBase = smem_u32(sW) + (((lane & 7) + ((lane >> 3) & 1)*8)*104 + (lane >> 4)*8) * 2;
    const uint32_t aOff  = ((mw*16 + (lane & 15))*104 + (lane >> 4)*8) * 2;

    int tile = blockIdx.x, buf = 0;
    if (tid < 128) stok[tid] = winrow_to_token(tile*128 + tid);
    __syncthreads();
    {
        const bf16* Ag = A + (size_t)tile*128*96;
        for (int idx = tid; idx < 1536; idx += 512) { int r = idx/12, c = idx%12; cp16(sA0 + r*104 + c*8, Ag + r*96 + c*8); }
        for (int idx = tid; idx < 3072; idx += 512) { int r = idx/24, c = idx%24; cp16(rst0 + r*96 + c*4, x + (size_t)stok[r]*96 + c*4); }
    }
    CPC();

    for (; tile < NUMTILES; tile += GRID) {
        CPW(); __syncthreads();
        uint32_t aBase = smem_u32(buf ? sA1 : sA0) + aOff;
        float*   rst   = buf ? rst1 : rst0;

        int nt = tile + GRID;
        int nb = buf ^ 1;
        if (tid < 128 && nt < NUMTILES) stok[nb*128 + tid] = winrow_to_token(nt*128 + tid);
        __syncthreads();
        if (nt < NUMTILES) {
            bf16*  sAn  = nb ? sA1 : sA0;
            float* rstn = nb ? rst1 : rst0;
            const int* st = stok + nb*128;
            const bf16* Ag = A + (size_t)nt*128*96;
            for (int idx = tid; idx < 1536; idx += 512) { int r = idx/12, c = idx%12; cp16(sAn + r*104 + c*8, Ag + r*96 + c*8); }
            for (int idx = tid; idx < 3072; idx += 512) { int r = idx/24, c = idx%24; cp16(rstn + r*96 + c*4, x + (size_t)st[r]*96 + c*4); }
        }
        CPC();

        float acc[6][4];
        #pragma unroll
        for (int f = 0; f < 6; f++) { acc[f][0]=0.f; acc[f][1]=0.f; acc[f][2]=0.f; acc[f][3]=0.f; }
        #pragma unroll
        for (int ks = 0; ks < 6; ks++) {
            uint32_t a0,a1,a2,a3;
            ldm_x4(a0,a1,a2,a3, aBase + ks*32);
            #pragma unroll
            for (int p = 0; p < 3; p++) {
                uint32_t b0,b1,b2,b3;
                ldm_x4t(b0,b1,b2,b3, wBase + (ks*16*104 + nw*48 + p*16)*2);
                mma16816(acc[2*p],   a0,a1,a2,a3, b0,b1);
                mma16816(acc[2*p+1], a0,a1,a2,a3, b2,b3);
            }
        }

        #pragma unroll
        for (int g = 0; g < 2; g++) {
            int rt = mw*16 + (lane >> 2) + 8*g;
            float s = 0.f, q = 0.f;
            #pragma unroll
            for (int p = 0; p < 6; p++) {
                #pragma unroll
                for (int t = 0; t < 2; t++) {
                    int col = nw*48 + p*8 + t2 + t;
                    float v = acc[p][2*g+t] + sbias[col] + rst[rt*96 + col];
                    acc[p][2*g+t] = v;
                    s += v;  q += v*v;
                }
            }
            s += __shfl_xor_sync(0xffffffffu, s, 1);
            s += __shfl_xor_sync(0xffffffffu, s, 2);
            q += __shfl_xor_sync(0xffffffffu, q, 1);
            q += __shfl_xor_sync(0xffffffffu, q, 2);
            if ((lane & 3) == 0) { sred[rt*4 + nw*2] = s; sred[rt*4 + nw*2 + 1] = q; }
        }
        __syncthreads();

        const int* st = stok + buf*128;
        #pragma unroll
        for (int g = 0; g < 2; g++) {
            int rt = mw*16 + (lane >> 2) + 8*g;
            float S = sred[rt*4]     + sred[rt*4 + 2];
            float Q = sred[rt*4 + 1] + sred[rt*4 + 3];
            float mu = S * (1.f/96.f);
            float var = Q * (1.f/96.f) - mu*mu;
            float rs = rsqrtf(var + 1e-5f);
            int tok = st[rt];
            #pragma unroll
            for (int p = 0; p < 6; p++) {
                int col = nw*48 + p*8 + t2;
                float v0 = acc[p][2*g], v1 = acc[p][2*g+1];
                float2 yy; yy.x = v0; yy.y = v1;
                *(float2*)(y + (size_t)tok*96 + col) = yy;
                __nv_bfloat162 hh = __floats2bfloat162_rn(
                    (v0-mu)*rs*sg[col]   + sb[col],
                    (v1-mu)*rs*sg[col+1] + sb[col+1]);
                *(uint32_t*)(hw + (size_t)tok*96 + col) = *(uint32_t*)&hh;
            }
        }
        buf ^= 1;
    }
}

// =====================================================================
// fused MLP kernel: 512 threads, M=256, 16 warps, kc unroll 2,
// fast-div gelu  [unchanged from R16]
// =====================================================================
__global__ void __launch_bounds__(512, 1)
mlp_kernel(const bf16* __restrict__ A, const float* __restrict__ W1,
           const float* __restrict__ b1f, const float* __restrict__ W2,
           const float* __restrict__ b2f, float* __restrict__ y)
{
    extern __shared__ __align__(16) char sm[];
    bf16*  sW1  = (bf16*)sm;                        // 75264
    bf16*  sW2  = (bf16*)(sm + 75264);              // 79872
    bf16*  sA   = (bf16*)(sm + 155136);             // 53248
    float* sb1  = (float*)(sm + 208384);            // 1536
    float* sb2  = (float*)(sm + 209920);            // 384 (total 210304)

    const int tid = threadIdx.x, warp = tid >> 5, lane = tid & 31;

    for (int i = tid; i < 96*384; i += 512) { int k = i/384, n = i%384; sW1[k*392+n] = __float2bfloat16(W1[i]); }
    for (int i = tid; i < 384*96; i += 512) { int k = i/96,  n = i%96;  sW2[k*104+n] = __float2bfloat16(W2[i]); }
    for (int i = tid; i < 384; i += 512) sb1[i] = b1f[i];
    if (tid < 96) sb2[tid] = b2f[tid];

    const uint32_t aBase  = smem_u32(sA) + ((warp*16 + (lane & 15))*104 + (lane >> 4)*8) * 2;
    const uint32_t w1Base = smem_u32(sW1) + (((lane & 7) + ((lane >> 3) & 1)*8)*392 + (lane >> 4)*8) * 2;
    const uint32_t w2Base = smem_u32(sW2) + (((lane & 7) + ((lane >> 3) & 1)*8)*104 + (lane >> 4)*8) * 2;
    const int t2 = (lane & 3)*2;

    int tile = blockIdx.x;
    {
        const bf16* Ag = A + (size_t)tile*256*96;
        for (int idx = tid; idx < 3072; idx += 512) { int r = idx/12, c = idx%12; cp16(sA + r*104 + c*8, Ag + r*96 + c*8); }
    }
    CPC();
    __syncthreads();

    for (; tile < NUMTILES2; tile += GRID) {
        CPW(); __syncthreads();

        uint32_t areg[6][4];
        #pragma unroll
        for (int ks = 0; ks < 6; ks++)
            ldm_x4(areg[ks][0], areg[ks][1], areg[ks][2], areg[ks][3], aBase + ks*32);
        __syncthreads();

        int nt = tile + GRID;
        if (nt < NUMTILES2) {
            const bf16* Ag = A + (size_t)nt*256*96;
            for (int idx = tid; idx < 3072; idx += 512) { int r = idx/12, c = idx%12; cp16(sA + r*104 + c*8, Ag + r*96 + c*8); }
        }
        CPC();

        float acc2[12][4];
        #pragma unroll
        for (int p = 0; p < 12; p++) { acc2[p][0]=0.f; acc2[p][1]=0.f; acc2[p][2]=0.f; acc2[p][3]=0.f; }

        #pragma unroll 2
        for (int kc = 0; kc < 24; kc++) {
            float h[8];
            #pragma unroll
            for (int i = 0; i < 8; i++) h[i] = 0.f;
            #pragma unroll
            for (int ks = 0; ks < 6; ks++) {
                uint32_t b0,b1,b2,b3;
                ldm_x4t(b0,b1,b2,b3, w1Base + (ks*16*392 + kc*16)*2);
                mma16816(h,   areg[ks][0], areg[ks][1], areg[ks][2], areg[ks][3], b0,b1);
                mma16816(h+4, areg[ks][0], areg[ks][1], areg[ks][2], areg[ks][3], b2,b3);
            }
            int c0 = kc*16 + t2;
            float z0 = sb1[c0], z1 = sb1[c0+1], z8 = sb1[c0+8], z9 = sb1[c0+9];
            float g0 = fast_gelu(h[0]+z0), g1 = fast_gelu(h[1]+z1);
            float g2 = fast_gelu(h[2]+z0), g3 = fast_gelu(h[3]+z1);
            float g4 = fast_gelu(h[4]+z8), g5 = fast_gelu(h[5]+z9);
            float g6 = fast_gelu(h[6]+z8), g7 = fast_gelu(h[7]+z9);
            __nv_bfloat162 q0 = __floats2bfloat162_rn(g0, g1);
            __nv_bfloat162 q1 = __floats2bfloat162_rn(g2, g3);
            __nv_bfloat162 q2 = __floats2bfloat162_rn(g4, g5);
            __nv_bfloat162 q3 = __floats2bfloat162_rn(g6, g7);
            uint32_t ha0 = *(uint32_t*)&q0, ha1 = *(uint32_t*)&q1;
            uint32_t ha2 = *(uint32_t*)&q2, ha3 = *(uint32_t*)&q3;
            #pragma unroll
            for (int p = 0; p < 6; p++) {
                uint32_t b0,b1,b2,b3;
                ldm_x4t(b0,b1,b2,b3, w2Base + (kc*16*104 + p*16)*2);
                mma16816(acc2[2*p],   ha0,ha1,ha2,ha3, b0,b1);
                mma16816(acc2[2*p+1], ha0,ha1,ha2,ha3, b2,b3);
            }
        }

        const int r0 = tile*256 + warp*16 + (lane >> 2);
        #pragma unroll
        for (int p = 0; p < 12; p++) {
            int col = p*8 + t2;
            float bz0 = sb2[col], bz1 = sb2[col+1];
            float2* p0 = (float2*)(y + (size_t)r0*96 + col);
            float2* p1 = (float2*)(y + (size_t)(r0+8)*96 + col);
            float2 v0 = *p0, v1 = *p1;
            v0.x += acc2[p][0] + bz0;  v0.y += acc2[p][1] + bz1;
            v1.x += acc2[p][2] + bz0;  v1.y += acc2[p][3] + bz1;
            *p0 = v0;  *p1 = v1;
        }
    }
}

// =====================================================================
// window attention (tensor cores): Q,K 56 rows unfilled, V 64 rows
// zero-filled; 5 blocks/SM; fast reciprocal in softmax
// =====================================================================
#define LDV 40
#define QKB 4480         // 56 rows x 80 B
#define HBUF 14080       // Q(4480) + K(4480) + V(5120)

__global__ void __launch_bounds__(96, 5)
attn_kernel(const bf16* __restrict__ qkv, const float* __restrict__ rpb,
            float* __restrict__ attn_w, bf16* __restrict__ outp)
{
    extern __shared__ __align__(16) char smA[];
    const int tid = threadIdx.x, warp = tid >> 5, lane = tid & 31;
    const int w = blockIdx.x, h = warp;
    char* sh = smA + warp*HBUF;
    int*   rowc = (int*)(smA + 3*HBUF);
    int*   colc = (int*)(smA + 3*HBUF + 256);
    float* srpb = (float*)(smA + 3*HBUF + 512);

    for (int i = lane; i < 75; i += 32) {
        int r = 49 + i/5, ch = i%5;
        *(uint4*)(sh + 2*QKB + (size_t)r*80 + ch*16) = make_uint4(0,0,0,0);
    }
    const bf16* base = qkv + (size_t)w*NN*288 + h*HD;
    for (int i = lane; i < 3*196; i += 32) {
        int which = i/196, rem = i%196;
        int n = rem >> 2, ch = rem & 3;
        uint4 v = *(const uint4*)(base + (size_t)n*288 + which*96 + ch*8);
        *(uint4*)(sh + which*QKB + (size_t)n*80 + ch*16) = v;
    }
    if (tid < 64) {
        int ic = tid < 49 ? tid : 48;
        int code = (ic/7)*13 + (ic%7);
        rowc[tid] = code;
        colc[tid] = 84 - code;
    }
    for (int i = tid; i < 507; i += 96) srpb[i] = rpb[(i%169)*3 + (i/169)];
    __syncthreads();

    const float* srpbh = srpb + h*169;
    const uint32_t sQu = smem_u32(sh), sKu = sQu + QKB, sVu = sQu + 2*QKB;
    const int lq = lane & 3, lr = lane >> 2;

    uint32_t kf[2][4][4];
    #pragma unroll
    for (int ks = 0; ks < 2; ks++)
        #pragma unroll
        for (int tp = 0; tp < 4; tp++)
            ldm_x4(kf[ks][tp][0], kf[ks][tp][1], kf[ks][tp][2], kf[ks][tp][3],
                   sKu + ((tp*16 + (lane&7) + ((lane>>4)&1)*8)*LDV)*2 + ((lane>>3)&1)*16 + ks*32);

    float* ap = attn_w ? attn_w + (size_t)(w*NHH + h)*(NN*NN) : (float*)0;
    const uint32_t vBase = sVu + (((lane&7) + ((lane>>3)&1)*8)*LDV + (lane>>4)*8)*2;

    #pragma unroll 1
    for (int mg = 0; mg < 2; mg++) {
        uint32_t qf[2][2][4];
        #pragma unroll
        for (int mt = 0; mt < 2; mt++)
            #pragma unroll
            for (int ks = 0; ks < 2; ks++)
                ldm_x4(qf[mt][ks][0], qf[mt][ks][1], qf[mt][ks][2], qf[mt][ks][3],
                       sQu + ((mg*32 + mt*16 + (lane&15))*LDV + (lane>>4)*8)*2 + ks*32);

        float S[2][7][4];
        #pragma unroll
        for (int mt = 0; mt < 2; mt++)
            #pragma unroll
            for (int nt = 0; nt < 7; nt++) {
                S[mt][nt][0]=0.f; S[mt][nt][1]=0.f; S[mt][nt][2]=0.f; S[mt][nt][3]=0.f;
                #pragma unroll
                for (int ks = 0; ks < 2; ks++)
                    mma16816(S[mt][nt], qf[mt][ks][0], qf[mt][ks][1], qf[mt][ks][2], qf[mt][ks][3],
                             kf[ks][nt>>1][(nt&1)*2], kf[ks][nt>>1][(nt&1)*2+1]);
            }

        float inv[2][2];
        #pragma unroll
        for (int mt = 0; mt < 2; mt++)
            #pragma unroll
            for (int g = 0; g < 2; g++) {
                int i = mg*32 + mt*16 + lr + 8*g;
                int rc = rowc[i];
                float s = 0.f;
                #pragma unroll
                for (int nt = 0; nt < 7; nt++) {
                    int j0 = nt*8 + 2*lq;
                    float b0 = srpbh[rc + colc[j0]];
                    float b1 = srpbh[rc + colc[j0+1]];
                    float e0 = (j0   < NN) ? __expf(S[mt][nt][2*g]  *SCALEV + b0) : 0.f;
                    float e1 = (j0+1 < NN) ? __expf(S[mt][nt][2*g+1]*SCALEV + b1) : 0.f;
                    S[mt][nt][2*g] = e0;  S[mt][nt][2*g+1] = e1;
                    s += e0 + e1;
                }
                s += __shfl_xor_sync(0xffffffffu, s, 1);
                s += __shfl_xor_sync(0xffffffffu, s, 2);
                inv[mt][g] = __fdividef(1.f, s);
            }
        #pragma unroll
        for (int mt = 0; mt < 2; mt++)
            #pragma unroll
            for (int g = 0; g < 2; g++) {
                int i = mg*32 + mt*16 + lr + 8*g;
                float iv = inv[mt][g];
                bool rowok = (i < NN);
                #pragma unroll
                for (int nt = 0; nt < 7; nt++) {
                    int j0 = nt*8 + 2*lq;
                    float e0 = S[mt][nt][2*g]   * iv;
                    float e1 = S[mt][nt][2*g+1] * iv;
                    S[mt][nt][2*g] = e0;  S[mt][nt][2*g+1] = e1;
                    if (ap && rowok) {
                        if (j0   < NN) ap[(size_t)i*NN + j0]     = e0;
                        if (j0+1 < NN) ap[(size_t)i*NN + j0 + 1] = e1;
                    }
                }
            }

        uint32_t paf[2][4][4];
        #pragma unroll
        for (int mt = 0; mt < 2; mt++)
            #pragma unroll
            for (int t = 0; t < 4; t++) {
                __nv_bfloat162 p0 = __floats2bfloat162_rn(S[mt][2*t][0], S[mt][2*t][1]);
                __nv_bfloat162 p1 = __floats2bfloat162_rn(S[mt][2*t][2], S[mt][2*t][3]);
                paf[mt][t][0] = *(uint32_t*)&p0;
                paf[mt][t][1] = *(uint32_t*)&p1;
                if (t < 3) {
                    __nv_bfloat162 p2 = __floats2bfloat162_rn(S[mt][2*t+1][0], S[mt][2*t+1][1]);
                    __nv_bfloat162 p3 = __floats2bfloat162_rn(S[mt][2*t+1][2], S[mt][2*t+1][3]);
                    paf[mt][t][2] = *(uint32_t*)&p2;
                    paf[mt][t][3] = *(uint32_t*)&p3;
                } else {
                    paf[mt][t][2] = 0u;  paf[mt][t][3] = 0u;
                }
            }

        float O[2][4][4];
        #pragma unroll
        for (int mt = 0; mt < 2; mt++)
            #pragma unroll
            for (int p = 0; p < 4; p++) { O[mt][p][0]=0.f; O[mt][p][1]=0.f; O[mt][p][2]=0.f; O[mt][p][3]=0.f; }
        #pragma unroll
        for (int ks = 0; ks < 4; ks++) {
            uint32_t vf[2][4];
            #pragma unroll
            for (int p = 0; p < 2; p++)
                ldm_x4t(vf[p][0], vf[p][1], vf[p][2], vf[p][3],
                        vBase + (ks*16*LDV + p*16)*2);
            #pragma unroll
            for (int mt = 0; mt < 2; mt++)
                #pragma unroll
                for (int p4 = 0; p4 < 4; p4++)
                    mma16816(O[mt][p4], paf[mt][ks][0], paf[mt][ks][1], paf[mt][ks][2], paf[mt][ks][3],
                             vf[p4>>1][(p4&1)*2], vf[p4>>1][(p4&1)*2+1]);
        }

        #pragma unroll
        for (int mt = 0; mt < 2; mt++)
            #pragma unroll
            for (int g = 0; g < 2; g++) {
                int i = mg*32 + mt*16 + lr + 8*g;
                if (i < NN) {
                    bf16* op = outp + (size_t)(w*NN + i)*CC + h*HD;
                    #pragma unroll
                    for (int p4 = 0; p4 < 4; p4++) {
                        __nv_bfloat162 pk = __floats2bfloat162_rn(O[mt][p4][2*g], O[mt][p4][2*g+1]);
                        *(uint32_t*)(op + p4*8 + 2*lq) = *(uint32_t*)&pk;
                    }
                }
            }
    }
}

// ---------------- launch ----------------
extern "C" void kernel_launch(void* const* d_in, const int* in_sizes, int n_in,
                              void* d_out, int out_size) {
    const float* x      = (const float*)d_in[0];
    const float* w_qkv  = (const float*)d_in[1];
    const float* b_qkv  = (const float*)d_in[2];
    const float* w_proj = (const float*)d_in[3];
    const float* b_proj = (const float*)d_in[4];
    const float* rpb    = (const float*)d_in[5];
    const float* gamma1 = (const float*)d_in[6];
    const float* beta1  = (const float*)d_in[7];
    const float* gamma2 = (const float*)d_in[8];
    const float* beta2  = (const float*)d_in[9];
    const float* w_fc1  = (const float*)d_in[10];
    const float* b_fc1  = (const float*)d_in[11];
    const float* w_fc2  = (const float*)d_in[12];
    const float* b_fc2  = (const float*)d_in[13];

    float* y = (float*)d_out;
    float* attn_w = ((long long)out_size >= YE + AE) ? (y + YE) : (float*)0;

    bf16 *p_hw, *p_qkv, *p_att;
    cudaGetSymbolAddress((void**)&p_hw,  g_hw);
    cudaGetSymbolAddress((void**)&p_qkv, g_qkv);
    cudaGetSymbolAddress((void**)&p_att, g_att);

    const int SMQ = 85888, SMP = 175744, SMM = 210304;
    const int SMA = 3*HBUF + 512 + 507*4 + 128;   // 44908 -> 5 blocks/SM
    cudaFuncSetAttribute(qkv_kernel, cudaFuncAttributeMaxDynamicSharedMemorySize, SMQ);
    cudaFuncSetAttribute(proj_kernel, cudaFuncAttributeMaxDynamicSharedMemorySize, SMP);
    cudaFuncSetAttribute(mlp_kernel,  cudaFuncAttributeMaxDynamicSharedMemorySize, SMM);
    cudaFuncSetAttribute(attn_kernel, cudaFuncAttributeMaxDynamicSharedMemorySize, SMA);

    // 1) fused LN1 + gather + qkv GEMM (2 CTAs/SM, direct loads)
    qkv_kernel<<<2*GRID, 512, SMQ>>>(x, w_qkv, b_qkv, gamma1, beta1, p_qkv);
    // 2) window attention, tensor cores (+ attn weights), 5 blocks/SM
    attn_kernel<<<BW, 96, SMA>>>(p_qkv, rpb, attn_w, p_att);
    // 3) proj GEMM + scatter + residual + LN2 (register epilogue) -> y, hw
    proj_kernel<<<GRID, 512, SMP>>>(p_att, w_proj, b_proj, x, gamma2, beta2, y, p_hw);
    // 4) fused MLP: fc1 + GELU(fast div) + fc2 + residual into y
    mlp_kernel<<<GRID, 512, SMM>>>(p_hw, w_fc1, b_fc1, w_fc2, b_fc2, y);
}